// round 5
// baseline (speedup 1.0000x reference)
#include <cuda_runtime.h>
#include <cuda_fp16.h>
#include <cstdint>

#define LDIM      256
#define BM        64
#define KC        64
#define NCH       4              // 256/64
#define NTHREADS  256

// ---- byte layout ----
#define A_BYTES    (64 * 128)             // 64 rows x 64 halves (128B) = 8KB
#define B_BYTES    (256 * 128)            // 32KB
#define STAGE_B    (A_BYTES + B_BYTES)    // 40KB
#define W1B        (2 * STAGE_B)          // 81920
#define W2B        (W1B + 1024)
#define LAMB       (W2B + 1024)
#define SREDB      (LAMB + 1024)
#define SMEM_BYTES (SREDB + 1024)         // 86016

__device__ __half2 g_Wh[LDIM * LDIM / 2];

// ---------------- helpers ----------------
__device__ __forceinline__ float sigf(float z) {
    return __fdividef(1.0f, 1.0f + __expf(-z));
}

__device__ __forceinline__ float gcdop(float l, float r, float w1, float w2, float lam) {
    float a  = fabsf(l * w1) + 1e-6f;
    float b  = fabsf(r * w2) + 1e-6f;
    float mn = fminf(a, b);
    float mx = fmaxf(a, b);
    return fmaf(lam, mn - mx, mx);
}

__device__ __forceinline__ void hmma16(float c[4],
                                       uint32_t a0, uint32_t a1, uint32_t a2, uint32_t a3,
                                       uint32_t b0, uint32_t b1) {
    asm volatile(
        "mma.sync.aligned.m16n8k16.row.col.f32.f16.f16.f32 "
        "{%0,%1,%2,%3},{%4,%5,%6,%7},{%8,%9},{%0,%1,%2,%3};"
        : "+f"(c[0]), "+f"(c[1]), "+f"(c[2]), "+f"(c[3])
        : "r"(a0), "r"(a1), "r"(a2), "r"(a3), "r"(b0), "r"(b1));
}

__device__ __forceinline__ void ldsm_x4(uint32_t r[4], uint32_t addr) {
    asm volatile("ldmatrix.sync.aligned.m8n8.x4.shared.b16 {%0,%1,%2,%3}, [%4];"
                 : "=r"(r[0]), "=r"(r[1]), "=r"(r[2]), "=r"(r[3]) : "r"(addr));
}

__device__ __forceinline__ uint32_t smem_u32(const void* p) {
    uint32_t a;
    asm("{ .reg .u64 t; cvta.to.shared.u64 t, %1; cvt.u32.u64 %0, t; }" : "=r"(a) : "l"(p));
    return a;
}

__device__ __forceinline__ void cp16(uint32_t s, const void* g) {
    uint64_t ga = __cvta_generic_to_global(g);
    asm volatile("cp.async.cg.shared.global [%0], [%1], 16;" :: "r"(s), "l"(ga));
}

// ---------------- W -> fp16 pre-pass ----------------
__global__ void conv_w_kernel(const float* __restrict__ W) {
    int i = blockIdx.x * 256 + threadIdx.x;     // 32768 half2
    float2 v = ((const float2*)W)[i];
    g_Wh[i] = __floats2half2_rn(v.x, v.y);
}

// ---------------- staging ----------------
struct AReg { uint4 u0, u1; };

__device__ __forceinline__ AReg ldA(const float* __restrict__ x, int row0, int c,
                                    int r, int q) {
    const float4* gp = (const float4*)(x + (size_t)(row0 + r) * LDIM + c * KC + q * 16);
    float4 f0 = __ldcs(gp);
    float4 f1 = __ldcs(gp + 1);
    float4 f2 = __ldcs(gp + 2);
    float4 f3 = __ldcs(gp + 3);
    AReg ar; __half2 h;
    h = __floats2half2_rn(f0.x, f0.y); ar.u0.x = *(uint32_t*)&h;
    h = __floats2half2_rn(f0.z, f0.w); ar.u0.y = *(uint32_t*)&h;
    h = __floats2half2_rn(f1.x, f1.y); ar.u0.z = *(uint32_t*)&h;
    h = __floats2half2_rn(f1.z, f1.w); ar.u0.w = *(uint32_t*)&h;
    h = __floats2half2_rn(f2.x, f2.y); ar.u1.x = *(uint32_t*)&h;
    h = __floats2half2_rn(f2.z, f2.w); ar.u1.y = *(uint32_t*)&h;
    h = __floats2half2_rn(f3.x, f3.y); ar.u1.z = *(uint32_t*)&h;
    h = __floats2half2_rn(f3.z, f3.w); ar.u1.w = *(uint32_t*)&h;
    return ar;
}

__device__ __forceinline__ void stA(char* sm, int buf, const AReg& ar, int r, int q) {
    char* base = sm + (size_t)buf * STAGE_B + (size_t)r * 128;
    int s = r & 7;
    *(uint4*)(base + (((2 * q)     ^ s) * 16)) = ar.u0;
    *(uint4*)(base + (((2 * q + 1) ^ s) * 16)) = ar.u1;
}

// B: each thread stages one full 128B row (8 cp.async.16)
__device__ __forceinline__ void cpB(uint32_t sbase, int buf, int c, int tid) {
    int n = tid;
    int s = n & 7;
    uint32_t brow = sbase + (uint32_t)buf * STAGE_B + A_BYTES + (uint32_t)n * 128u;
    const __half* g = (const __half*)g_Wh + (size_t)n * LDIM + c * KC;
    #pragma unroll
    for (int j = 0; j < 8; j++)
        cp16(brow + (uint32_t)((j ^ s) * 16), g + j * 8);
    asm volatile("cp.async.commit_group;");
}

// ---------------- main kernel ----------------
__global__ void __launch_bounds__(NTHREADS, 2)
btln_main_kernel(const float* __restrict__ x,
                 const float* __restrict__ wts,
                 const float* __restrict__ bias,
                 const float* __restrict__ w_out,
                 const float* __restrict__ b_out,
                 float* __restrict__ out)
{
    extern __shared__ char sm[];
    float* sw1  = (float*)(sm + W1B);
    float* sw2  = (float*)(sm + W2B);
    float* slam = (float*)(sm + LAMB);
    float* sred = (float*)(sm + SREDB);
    const uint32_t sbase = smem_u32(sm);

    const int tid  = threadIdx.x;
    const int lane = tid & 31;
    const int wid  = tid >> 5;
    const int gid  = lane >> 2;
    const int tig  = lane & 3;
    const int wm   = wid & 1;      // 2 bands of 32 rows
    const int wn   = wid >> 1;     // 4 bands of 64 cols
    const int row0 = blockIdx.x * BM;
    const int ar_r = tid >> 2;     // staging row 0..63
    const int ar_q = tid & 3;

    if (tid < 255) {
        sw1[tid]  = wts[2 * tid];
        sw2[tid]  = wts[2 * tid + 1];
        slam[tid] = sigf(bias[tid]);
    }

    float cacc[2][8][4];
    #pragma unroll
    for (int mt = 0; mt < 2; mt++)
        #pragma unroll
        for (int nt = 0; nt < 8; nt++)
            #pragma unroll
            for (int i = 0; i < 4; i++) cacc[mt][nt][i] = 0.0f;

    // prologue: stage chunk 0
    {
        AReg a0 = ldA(x, row0, 0, ar_r, ar_q);
        cpB(sbase, 0, 0, tid);
        stA(sm, 0, a0, ar_r, ar_q);
    }

    const int a_rl  = lane & 15;
    const int a_ch  = lane >> 4;
    const int b_rl  = ((lane >> 4) << 3) | (lane & 7);
    const int b_ch  = (lane >> 3) & 1;

    #pragma unroll 1
    for (int c = 0; c < NCH; c++) {
        const int buf = c & 1;
        AReg an;
        if (c + 1 < NCH) {
            cpB(sbase, buf ^ 1, c + 1, tid);
            an = ldA(x, row0, c + 1, ar_r, ar_q);
            asm volatile("cp.async.wait_group 1;" ::: "memory");
        } else {
            asm volatile("cp.async.wait_group 0;" ::: "memory");
        }
        __syncthreads();

        const uint32_t smA = sbase + (uint32_t)buf * STAGE_B;
        const uint32_t smB = smA + A_BYTES;

        #pragma unroll
        for (int ks = 0; ks < 4; ks++) {
            uint32_t a[2][4];
            #pragma unroll
            for (int mt = 0; mt < 2; mt++) {
                int row = wm * 32 + mt * 16 + a_rl;
                int ch  = (ks * 2 + a_ch) ^ (row & 7);
                ldsm_x4(a[mt], smA + (uint32_t)(row * 128 + ch * 16));
            }
            uint32_t b[8][2];
            #pragma unroll
            for (int ntp = 0; ntp < 4; ntp++) {
                int row = wn * 64 + ntp * 16 + b_rl;
                int ch  = (ks * 2 + b_ch) ^ (row & 7);
                uint32_t r4[4];
                ldsm_x4(r4, smB + (uint32_t)(row * 128 + ch * 16));
                b[2 * ntp][0]     = r4[0];
                b[2 * ntp][1]     = r4[1];
                b[2 * ntp + 1][0] = r4[2];
                b[2 * ntp + 1][1] = r4[3];
            }
            #pragma unroll
            for (int mt = 0; mt < 2; mt++)
                #pragma unroll
                for (int nt = 0; nt < 8; nt++)
                    hmma16(cacc[mt][nt], a[mt][0], a[mt][1], a[mt][2], a[mt][3],
                           b[nt][0], b[nt][1]);
        }

        if (c + 1 < NCH) stA(sm, buf ^ 1, an, ar_r, ar_q);
        __syncthreads();
    }

    // -------- epilogue: leaf sigmoid + tree (registers + shuffles) --------
    float v[4][8];

    // L1 (off 0): j = wn*32 + nt*4 + tig
    #pragma unroll
    for (int nt = 0; nt < 8; nt++) {
        int j = wn * 32 + nt * 4 + tig;
        float w1 = sw1[j], w2 = sw2[j], lm = slam[j];
        #pragma unroll
        for (int rw = 0; rw < 4; rw++) {
            int mt = rw >> 1, hh = rw & 1;
            float l = sigf(cacc[mt][nt][hh * 2]     - 2.0f);
            float r = sigf(cacc[mt][nt][hh * 2 + 1] - 2.0f);
            v[rw][nt] = gcdop(l, r, w1, w2, lm);
        }
    }
    // L2 (off 128): shfl_xor 1
    #pragma unroll
    for (int nt = 0; nt < 8; nt++) {
        int j = 128 + wn * 16 + nt * 2 + (tig >> 1);
        float w1 = sw1[j], w2 = sw2[j], lm = slam[j];
        #pragma unroll
        for (int rw = 0; rw < 4; rw++) {
            float o = __shfl_xor_sync(0xffffffffu, v[rw][nt], 1);
            float l = (tig & 1) ? o : v[rw][nt];
            float r = (tig & 1) ? v[rw][nt] : o;
            v[rw][nt] = gcdop(l, r, w1, w2, lm);
        }
    }
    // L3 (off 192): shfl_xor 2
    #pragma unroll
    for (int nt = 0; nt < 8; nt++) {
        int j = 192 + wn * 8 + nt;
        float w1 = sw1[j], w2 = sw2[j], lm = slam[j];
        #pragma unroll
        for (int rw = 0; rw < 4; rw++) {
            float o = __shfl_xor_sync(0xffffffffu, v[rw][nt], 2);
            float l = (tig & 2) ? o : v[rw][nt];
            float r = (tig & 2) ? v[rw][nt] : o;
            v[rw][nt] = gcdop(l, r, w1, w2, lm);
        }
    }
    // L4 (off 224)
    #pragma unroll
    for (int p = 0; p < 4; p++) {
        int j = 224 + wn * 4 + p;
        float w1 = sw1[j], w2 = sw2[j], lm = slam[j];
        #pragma unroll
        for (int rw = 0; rw < 4; rw++)
            v[rw][p] = gcdop(v[rw][2 * p], v[rw][2 * p + 1], w1, w2, lm);
    }
    // L5 (off 240)
    #pragma unroll
    for (int q = 0; q < 2; q++) {
        int j = 240 + wn * 2 + q;
        float w1 = sw1[j], w2 = sw2[j], lm = slam[j];
        #pragma unroll
        for (int rw = 0; rw < 4; rw++)
            v[rw][q] = gcdop(v[rw][2 * q], v[rw][2 * q + 1], w1, w2, lm);
    }
    // L6 (off 248) -> sred[row][wn]
    {
        int j = 248 + wn;
        float w1 = sw1[j], w2 = sw2[j], lm = slam[j];
        #pragma unroll
        for (int rw = 0; rw < 4; rw++) {
            float v6  = gcdop(v[rw][0], v[rw][1], w1, w2, lm);
            int   row = wm * 32 + (rw >> 1) * 16 + gid + (rw & 1) * 8;
            sred[row * 4 + wn] = v6;
        }
    }
    __syncthreads();

    // L7 (off 252/253) + L8 (off 254) + output
    if (tid < BM) {
        float4 s4   = *(const float4*)(sred + tid * 4);
        float  aa   = gcdop(s4.x, s4.y, sw1[252], sw2[252], slam[252]);
        float  bb   = gcdop(s4.z, s4.w, sw1[253], sw2[253], slam[253]);
        float  root = gcdop(aa, bb, sw1[254], sw2[254], slam[254]);
        out[row0 + tid] = sigf(fmaf(root, w_out[0], b_out[0]));
    }
}

extern "C" void kernel_launch(void* const* d_in, const int* in_sizes, int n_in,
                              void* d_out, int out_size) {
    const float* x     = (const float*)d_in[0];
    const float* W     = (const float*)d_in[1];
    const float* wts   = (const float*)d_in[2];
    const float* bias  = (const float*)d_in[3];
    const float* w_out = (const float*)d_in[4];
    const float* b_out = (const float*)d_in[5];
    float* out = (float*)d_out;

    const int Brows = in_sizes[0] / LDIM;   // 65536
    const int grid  = Brows / BM;           // 1024

    conv_w_kernel<<<LDIM * LDIM / 2 / 256, 256>>>(W);

    cudaFuncSetAttribute(btln_main_kernel,
                         cudaFuncAttributeMaxDynamicSharedMemorySize, SMEM_BYTES);
    btln_main_kernel<<<grid, NTHREADS, SMEM_BYTES>>>(x, wts, bias, w_out, b_out, out);
}

// round 6
// speedup vs baseline: 1.3099x; 1.3099x over previous
#include <cuda_runtime.h>
#include <cuda_fp16.h>
#include <cstdint>

#define LDIM      256
#define BM        128
#define KC        64
#define NCH       4              // 256/64
#define NTHREADS  1024

// ---- byte layout ----
#define A_BYTES    (128 * 128)            // 128 rows x 64 halves = 16KB
#define B_BYTES    (256 * 128)            // 32KB
#define STAGE_B    (A_BYTES + B_BYTES)    // 48KB
#define W1B        (2 * STAGE_B)          // 98304
#define W2B        (W1B + 1024)
#define LAMB       (W2B + 1024)
#define SREDB      (LAMB + 1024)
#define SMEM_BYTES (SREDB + 2048)         // 103424

__device__ __half2 g_Wh[LDIM * LDIM / 2];

// ---------------- helpers ----------------
__device__ __forceinline__ float sigf(float z) {
    return __fdividef(1.0f, 1.0f + __expf(-z));
}

__device__ __forceinline__ float gcdop(float l, float r, float w1, float w2, float lam) {
    float a  = fabsf(l * w1) + 1e-6f;
    float b  = fabsf(r * w2) + 1e-6f;
    float mn = fminf(a, b);
    float mx = fmaxf(a, b);
    return fmaf(lam, mn - mx, mx);
}

__device__ __forceinline__ void hmma16(float c[4],
                                       uint32_t a0, uint32_t a1, uint32_t a2, uint32_t a3,
                                       uint32_t b0, uint32_t b1) {
    asm volatile(
        "mma.sync.aligned.m16n8k16.row.col.f32.f16.f16.f32 "
        "{%0,%1,%2,%3},{%4,%5,%6,%7},{%8,%9},{%0,%1,%2,%3};"
        : "+f"(c[0]), "+f"(c[1]), "+f"(c[2]), "+f"(c[3])
        : "r"(a0), "r"(a1), "r"(a2), "r"(a3), "r"(b0), "r"(b1));
}

__device__ __forceinline__ void ldsm_x4(uint32_t r[4], uint32_t addr) {
    asm volatile("ldmatrix.sync.aligned.m8n8.x4.shared.b16 {%0,%1,%2,%3}, [%4];"
                 : "=r"(r[0]), "=r"(r[1]), "=r"(r[2]), "=r"(r[3]) : "r"(addr));
}

__device__ __forceinline__ uint32_t smem_u32(const void* p) {
    uint32_t a;
    asm("{ .reg .u64 t; cvta.to.shared.u64 t, %1; cvt.u32.u64 %0, t; }" : "=r"(a) : "l"(p));
    return a;
}

__device__ __forceinline__ void cp16(uint32_t s, const void* g) {
    uint64_t ga = __cvta_generic_to_global(g);
    asm volatile("cp.async.cg.shared.global [%0], [%1], 16;" :: "r"(s), "l"(ga));
}

// ---------------- W -> fp16 pre-pass ----------------
__global__ void conv_w_kernel(const float* __restrict__ W) {
    int i = blockIdx.x * 256 + threadIdx.x;     // 32768 half2
    float2 v = ((const float2*)W)[i];
    g_Wh[i] = __floats2half2_rn(v.x, v.y);
}

// ---------------- staging ----------------
// A: each thread stages 8 halves (one 16B slot). r = tid>>3 (0..127), q = tid&7.
__device__ __forceinline__ uint4 ldA(const float* __restrict__ x, int row0, int c,
                                     int r, int q) {
    const float4* gp = (const float4*)(x + (size_t)(row0 + r) * LDIM + c * KC + q * 8);
    float4 f0 = __ldcs(gp);
    float4 f1 = __ldcs(gp + 1);
    uint4 u; __half2 h;
    h = __floats2half2_rn(f0.x, f0.y); u.x = *(uint32_t*)&h;
    h = __floats2half2_rn(f0.z, f0.w); u.y = *(uint32_t*)&h;
    h = __floats2half2_rn(f1.x, f1.y); u.z = *(uint32_t*)&h;
    h = __floats2half2_rn(f1.z, f1.w); u.w = *(uint32_t*)&h;
    return u;
}

__device__ __forceinline__ void stA(char* sm, int buf, uint4 u, int r, int q) {
    char* base = sm + (size_t)buf * STAGE_B + (size_t)r * 128;
    *(uint4*)(base + ((q ^ (r & 7)) * 16)) = u;
}

// B: 256 rows x 128B; each thread stages a quarter-row (2 cp16).
__device__ __forceinline__ void cpB(uint32_t sbase, int buf, int c, int tid) {
    int n = tid >> 2, qq = tid & 3;
    int s = n & 7;
    uint32_t brow = sbase + (uint32_t)buf * STAGE_B + A_BYTES + (uint32_t)n * 128u;
    const __half* g = (const __half*)g_Wh + (size_t)n * LDIM + c * KC + qq * 16;
    cp16(brow + (uint32_t)(((2 * qq)     ^ s) * 16), g);
    cp16(brow + (uint32_t)(((2 * qq + 1) ^ s) * 16), g + 8);
    asm volatile("cp.async.commit_group;");
}

// ---------------- main kernel ----------------
__global__ void __launch_bounds__(NTHREADS, 1)
btln_main_kernel(const float* __restrict__ x,
                 const float* __restrict__ wts,
                 const float* __restrict__ bias,
                 const float* __restrict__ w_out,
                 const float* __restrict__ b_out,
                 float* __restrict__ out)
{
    extern __shared__ char sm[];
    float* sw1  = (float*)(sm + W1B);
    float* sw2  = (float*)(sm + W2B);
    float* slam = (float*)(sm + LAMB);
    float* sred = (float*)(sm + SREDB);
    const uint32_t sbase = smem_u32(sm);

    const int tid  = threadIdx.x;
    const int lane = tid & 31;
    const int wid  = tid >> 5;            // 0..31
    const int gid  = lane >> 2;
    const int tig  = lane & 3;
    const int wn   = wid & 3;             // N band of 64 cols
    const int wm   = wid >> 2;            // M band of 16 rows (0..7)
    const int row0 = blockIdx.x * BM;
    const int ar_r = tid >> 3;            // staging row 0..127
    const int ar_q = tid & 7;

    if (tid < 255) {
        sw1[tid]  = wts[2 * tid];
        sw2[tid]  = wts[2 * tid + 1];
        slam[tid] = sigf(bias[tid]);
    }

    float cacc[8][4];
    #pragma unroll
    for (int nt = 0; nt < 8; nt++)
        #pragma unroll
        for (int i = 0; i < 4; i++) cacc[nt][i] = 0.0f;

    // prologue: stage chunk 0
    {
        uint4 a0 = ldA(x, row0, 0, ar_r, ar_q);
        cpB(sbase, 0, 0, tid);
        stA(sm, 0, a0, ar_r, ar_q);
    }

    const int a_rl = lane & 15;
    const int a_ch = lane >> 4;
    const int b_rl = ((lane >> 4) << 3) | (lane & 7);
    const int b_ch = (lane >> 3) & 1;

    #pragma unroll 1
    for (int c = 0; c < NCH; c++) {
        const int buf = c & 1;
        uint4 an;
        if (c + 1 < NCH) {
            cpB(sbase, buf ^ 1, c + 1, tid);
            an = ldA(x, row0, c + 1, ar_r, ar_q);
            asm volatile("cp.async.wait_group 1;" ::: "memory");
        } else {
            asm volatile("cp.async.wait_group 0;" ::: "memory");
        }
        __syncthreads();

        const uint32_t smA = sbase + (uint32_t)buf * STAGE_B;
        const uint32_t smB = smA + A_BYTES;

        #pragma unroll
        for (int ks = 0; ks < 4; ks++) {
            uint32_t a[4];
            {
                int row = wm * 16 + a_rl;
                int ch  = (ks * 2 + a_ch) ^ (row & 7);
                ldsm_x4(a, smA + (uint32_t)(row * 128 + ch * 16));
            }
            #pragma unroll
            for (int ntp = 0; ntp < 4; ntp++) {
                int row = wn * 64 + ntp * 16 + b_rl;
                int ch  = (ks * 2 + b_ch) ^ (row & 7);
                uint32_t b4[4];
                ldsm_x4(b4, smB + (uint32_t)(row * 128 + ch * 16));
                hmma16(cacc[2 * ntp],     a[0], a[1], a[2], a[3], b4[0], b4[1]);
                hmma16(cacc[2 * ntp + 1], a[0], a[1], a[2], a[3], b4[2], b4[3]);
            }
        }

        if (c + 1 < NCH) stA(sm, buf ^ 1, an, ar_r, ar_q);
        __syncthreads();
    }

    // -------- epilogue: leaf sigmoid + tree (registers + shuffles) --------
    float v[2][8];

    // L1 (off 0): j = wn*32 + nt*4 + tig
    #pragma unroll
    for (int nt = 0; nt < 8; nt++) {
        int j = wn * 32 + nt * 4 + tig;
        float w1 = sw1[j], w2 = sw2[j], lm = slam[j];
        #pragma unroll
        for (int rw = 0; rw < 2; rw++) {
            float l = sigf(cacc[nt][rw * 2]     - 2.0f);
            float r = sigf(cacc[nt][rw * 2 + 1] - 2.0f);
            v[rw][nt] = gcdop(l, r, w1, w2, lm);
        }
    }
    // L2 (off 128): shfl_xor 1
    #pragma unroll
    for (int nt = 0; nt < 8; nt++) {
        int j = 128 + wn * 16 + nt * 2 + (tig >> 1);
        float w1 = sw1[j], w2 = sw2[j], lm = slam[j];
        #pragma unroll
        for (int rw = 0; rw < 2; rw++) {
            float o = __shfl_xor_sync(0xffffffffu, v[rw][nt], 1);
            float l = (tig & 1) ? o : v[rw][nt];
            float r = (tig & 1) ? v[rw][nt] : o;
            v[rw][nt] = gcdop(l, r, w1, w2, lm);
        }
    }
    // L3 (off 192): shfl_xor 2
    #pragma unroll
    for (int nt = 0; nt < 8; nt++) {
        int j = 192 + wn * 8 + nt;
        float w1 = sw1[j], w2 = sw2[j], lm = slam[j];
        #pragma unroll
        for (int rw = 0; rw < 2; rw++) {
            float o = __shfl_xor_sync(0xffffffffu, v[rw][nt], 2);
            float l = (tig & 2) ? o : v[rw][nt];
            float r = (tig & 2) ? v[rw][nt] : o;
            v[rw][nt] = gcdop(l, r, w1, w2, lm);
        }
    }
    // L4 (off 224)
    #pragma unroll
    for (int p = 0; p < 4; p++) {
        int j = 224 + wn * 4 + p;
        float w1 = sw1[j], w2 = sw2[j], lm = slam[j];
        #pragma unroll
        for (int rw = 0; rw < 2; rw++)
            v[rw][p] = gcdop(v[rw][2 * p], v[rw][2 * p + 1], w1, w2, lm);
    }
    // L5 (off 240)
    #pragma unroll
    for (int q = 0; q < 2; q++) {
        int j = 240 + wn * 2 + q;
        float w1 = sw1[j], w2 = sw2[j], lm = slam[j];
        #pragma unroll
        for (int rw = 0; rw < 2; rw++)
            v[rw][q] = gcdop(v[rw][2 * q], v[rw][2 * q + 1], w1, w2, lm);
    }
    // L6 (off 248) -> sred[row][wn]
    {
        int j = 248 + wn;
        float w1 = sw1[j], w2 = sw2[j], lm = slam[j];
        #pragma unroll
        for (int rw = 0; rw < 2; rw++) {
            float v6  = gcdop(v[rw][0], v[rw][1], w1, w2, lm);
            int   row = wm * 16 + gid + rw * 8;
            sred[row * 4 + wn] = v6;
        }
    }
    __syncthreads();

    // L7 (off 252/253) + L8 (off 254) + output
    if (tid < BM) {
        float4 s4   = *(const float4*)(sred + tid * 4);
        float  aa   = gcdop(s4.x, s4.y, sw1[252], sw2[252], slam[252]);
        float  bb   = gcdop(s4.z, s4.w, sw1[253], sw2[253], slam[253]);
        float  root = gcdop(aa, bb, sw1[254], sw2[254], slam[254]);
        out[row0 + tid] = sigf(fmaf(root, w_out[0], b_out[0]));
    }
}

extern "C" void kernel_launch(void* const* d_in, const int* in_sizes, int n_in,
                              void* d_out, int out_size) {
    const float* x     = (const float*)d_in[0];
    const float* W     = (const float*)d_in[1];
    const float* wts   = (const float*)d_in[2];
    const float* bias  = (const float*)d_in[3];
    const float* w_out = (const float*)d_in[4];
    const float* b_out = (const float*)d_in[5];
    float* out = (float*)d_out;

    const int Brows = in_sizes[0] / LDIM;   // 65536
    const int grid  = Brows / BM;           // 512

    conv_w_kernel<<<LDIM * LDIM / 2 / 256, 256>>>(W);

    cudaFuncSetAttribute(btln_main_kernel,
                         cudaFuncAttributeMaxDynamicSharedMemorySize, SMEM_BYTES);
    btln_main_kernel<<<grid, NTHREADS, SMEM_BYTES>>>(x, wts, bias, w_out, b_out, out);
}